// round 15
// baseline (speedup 1.0000x reference)
#include <cuda_runtime.h>

#define N_NODES 50000
#define N_EDGES 800000
#define D 64
#define BN_EPS 1e-5f

// ---------------------------------------------------------------------------
// Scratch (__device__ globals; no cudaMalloc allowed)
// ---------------------------------------------------------------------------
__device__ __align__(16) float g_h[N_NODES * D];     // pre-BN hidden
__device__ int   g_deg[N_NODES];
__device__ int   g_rowptr[N_NODES + 1];
__device__ int   g_cursor[N_NODES];
__device__ int   g_srcs[N_EDGES];                    // src ids sorted by dst
__device__ float g_sum[D];
__device__ float g_sumsq[D];
__device__ float g_scale[D];
__device__ float g_shift[D];

__device__ __forceinline__ int clampid(int v) {
    v = v < 0 ? 0 : v;
    return v >= N_NODES ? (N_NODES - 1) : v;
}

// ---------------------------------------------------------------------------
// CSR build step 1: zero degree histogram
// ---------------------------------------------------------------------------
__global__ void k_deg_zero() {
    int i = blockIdx.x * blockDim.x + threadIdx.x;
    if (i < N_NODES) g_deg[i] = 0;
}

// CSR build step 2: histogram of dst. 4 edges per thread, all loads batched
// up front so 4 independent atomics are in flight (MLP=4).
__global__ void k_hist(const int* __restrict__ ei) {
    int t = blockIdx.x * blockDim.x + threadIdx.x;
    int stride = gridDim.x * blockDim.x;
    int d[4];
#pragma unroll
    for (int k = 0; k < 4; k++) {
        int e = t + k * stride;
        d[k] = (e < N_EDGES) ? clampid(__ldg(&ei[N_EDGES + e])) : -1;
    }
#pragma unroll
    for (int k = 0; k < 4; k++)
        if (d[k] >= 0) atomicAdd(&g_deg[d[k]], 1);
}

// CSR build step 3: exclusive prefix scan (single block, 1024 threads)
__global__ void k_scan() {
    __shared__ int part[1024];
    const int CH = (N_NODES + 1023) / 1024;   // 49
    int t = threadIdx.x;
    int base = t * CH;

    int s = 0;
    for (int i = 0; i < CH; i++) {
        int idx = base + i;
        if (idx < N_NODES) s += g_deg[idx];
    }
    part[t] = s;
    __syncthreads();
    for (int off = 1; off < 1024; off <<= 1) {
        int v = (t >= off) ? part[t - off] : 0;
        __syncthreads();
        part[t] += v;
        __syncthreads();
    }
    int running = part[t] - s;
    for (int i = 0; i < CH; i++) {
        int idx = base + i;
        if (idx < N_NODES) {
            g_rowptr[idx] = running;
            g_cursor[idx] = running;
            running += g_deg[idx];
        }
    }
    if (t == 1023) g_rowptr[N_NODES] = part[1023];
    if (t < D) { g_sum[t] = 0.f; g_sumsq[t] = 0.f; }   // zero layer-0 BN stats
}

// CSR build step 4: scatter src ids into dst-sorted order. 4 edges per
// thread, loads batched, 4 independent atomic-returns in flight.
__global__ void k_fill(const int* __restrict__ ei) {
    int t = blockIdx.x * blockDim.x + threadIdx.x;
    int stride = gridDim.x * blockDim.x;
    int s[4], d[4], pos[4];
#pragma unroll
    for (int k = 0; k < 4; k++) {
        int e = t + k * stride;
        if (e < N_EDGES) {
            s[k] = clampid(__ldg(&ei[e]));
            d[k] = clampid(__ldg(&ei[N_EDGES + e]));
        } else {
            s[k] = -1; d[k] = -1;
        }
    }
#pragma unroll
    for (int k = 0; k < 4; k++)
        pos[k] = (d[k] >= 0) ? atomicAdd(&g_cursor[d[k]], 1) : 0;
#pragma unroll
    for (int k = 0; k < 4; k++)
        if (d[k] >= 0) g_srcs[pos[k]] = s[k];
}

// ---------------------------------------------------------------------------
// FUSED gather + MLP stage 1, gather loop unrolled x4 for MLP.
// Block = 256 threads handles 32 nodes (16 lanes per node, 1 float4/lane).
// ---------------------------------------------------------------------------
__global__ void k_gmlp1(const float* __restrict__ xin,
                        const float* __restrict__ W,
                        const float* __restrict__ b) {
    __shared__ float sW[D * D];                     // 16 KB
    __shared__ __align__(16) float sIn[32][D];      // 8 KB
    __shared__ float sRed[2][4][D];                 // 2 KB

    int tid = threadIdx.x;
    for (int i = tid; i < D * D; i += 256) sW[i] = W[i];

    int row0 = blockIdx.x * 32;
    const float4* x4 = reinterpret_cast<const float4*>(xin);
    int sub  = tid >> 4;     // 0..15
    int lane = tid & 15;     // float4 slot within the row

#pragma unroll
    for (int half = 0; half < 2; half++) {
        int r = sub + half * 16;
        int node = row0 + r;
        float4 acc = make_float4(0.f, 0.f, 0.f, 0.f);
        if (node < N_NODES) {
            acc = __ldg(&x4[node * 16 + lane]);          // self term (eps=0)
            int beg = g_rowptr[node];
            int end = g_rowptr[node + 1];
            int e = beg;
            for (; e + 4 <= end; e += 4) {               // 4 rows in flight
                int s0 = __ldg(&g_srcs[e]);
                int s1 = __ldg(&g_srcs[e + 1]);
                int s2 = __ldg(&g_srcs[e + 2]);
                int s3 = __ldg(&g_srcs[e + 3]);
                float4 v0 = __ldg(&x4[s0 * 16 + lane]);
                float4 v1 = __ldg(&x4[s1 * 16 + lane]);
                float4 v2 = __ldg(&x4[s2 * 16 + lane]);
                float4 v3 = __ldg(&x4[s3 * 16 + lane]);
                acc.x += (v0.x + v1.x) + (v2.x + v3.x);
                acc.y += (v0.y + v1.y) + (v2.y + v3.y);
                acc.z += (v0.z + v1.z) + (v2.z + v3.z);
                acc.w += (v0.w + v1.w) + (v2.w + v3.w);
            }
            for (; e < end; e++) {
                int s0 = __ldg(&g_srcs[e]);
                float4 v0 = __ldg(&x4[s0 * 16 + lane]);
                acc.x += v0.x; acc.y += v0.y; acc.z += v0.z; acc.w += v0.w;
            }
        }
        *reinterpret_cast<float4*>(&sIn[r][lane * 4]) = acc;
    }
    __syncthreads();

    int c  = tid & 63;
    int r0 = tid >> 6;   // 0..3
    float acc[8];
#pragma unroll
    for (int rr = 0; rr < 8; rr++) acc[rr] = 0.f;

#pragma unroll 8
    for (int k = 0; k < D; k++) {
        float w = sW[k * D + c];
#pragma unroll
        for (int rr = 0; rr < 8; rr++)
            acc[rr] += sIn[r0 + rr * 4][k] * w;
    }

    float bias = b[c];
    float s = 0.f, ss = 0.f;
#pragma unroll
    for (int rr = 0; rr < 8; rr++) {
        int gr = row0 + r0 + rr * 4;
        if (gr < N_NODES) {
            float h = acc[rr] + bias;
            g_h[gr * D + c] = h;
            s  += h;
            ss += h * h;
        }
    }
    sRed[0][r0][c] = s;
    sRed[1][r0][c] = ss;
    __syncthreads();
    if (r0 == 0) {
        float ts  = sRed[0][0][c] + sRed[0][1][c] + sRed[0][2][c] + sRed[0][3][c];
        float tss = sRed[1][0][c] + sRed[1][1][c] + sRed[1][2][c] + sRed[1][3][c];
        atomicAdd(&g_sum[c], ts);
        atomicAdd(&g_sumsq[c], tss);
    }
}

// ---------------------------------------------------------------------------
// Finalize BN affine, then zero the stats for the next layer.
// ---------------------------------------------------------------------------
__global__ void k_bnfin(const float* __restrict__ g,
                        const float* __restrict__ beta) {
    int c = threadIdx.x;
    float inv_n = 1.0f / (float)N_NODES;
    float mean = g_sum[c] * inv_n;
    float var  = g_sumsq[c] * inv_n - mean * mean;
    float sc = g[c] * rsqrtf(var + BN_EPS);
    g_scale[c] = sc;
    g_shift[c] = beta[c] - mean * sc;
    g_sum[c] = 0.f;
    g_sumsq[c] = 0.f;
}

// ---------------------------------------------------------------------------
// MLP stage 2: out = relu( relu(BN(h)) @ W2 + b2 )
// ---------------------------------------------------------------------------
__global__ void k_mlp2(const float* __restrict__ W,
                       const float* __restrict__ b,
                       float* __restrict__ outp) {
    __shared__ float sW[D * D];
    __shared__ float sIn[32][D];

    int tid = threadIdx.x;
    for (int i = tid; i < D * D; i += 256) sW[i] = W[i];

    int row0 = blockIdx.x * 32;
    for (int i = tid; i < 32 * D; i += 256) {
        int r = i >> 6, cc = i & 63;
        int gr = row0 + r;
        float v = 0.f;
        if (gr < N_NODES)
            v = fmaxf(g_h[gr * D + cc] * g_scale[cc] + g_shift[cc], 0.f);
        sIn[r][cc] = v;
    }
    __syncthreads();

    int c  = tid & 63;
    int r0 = tid >> 6;
    float acc[8];
#pragma unroll
    for (int rr = 0; rr < 8; rr++) acc[rr] = 0.f;

#pragma unroll 8
    for (int k = 0; k < D; k++) {
        float w = sW[k * D + c];
#pragma unroll
        for (int rr = 0; rr < 8; rr++)
            acc[rr] += sIn[r0 + rr * 4][k] * w;
    }

    float bias = b[c];
#pragma unroll
    for (int rr = 0; rr < 8; rr++) {
        int gr = row0 + r0 + rr * 4;
        if (gr < N_NODES)
            outp[gr * D + c] = fmaxf(acc[rr] + bias, 0.f);
    }
}

// ---------------------------------------------------------------------------
// Launch
// ---------------------------------------------------------------------------
extern "C" void kernel_launch(void* const* d_in, const int* in_sizes, int n_in,
                              void* d_out, int out_size) {
    const float* x   = (const float*)d_in[0];
    const int*   ei  = (const int*)d_in[1];          // int32 (JAX x64 demotion)
    const float *W1_0 = (const float*)d_in[2],  *b1_0 = (const float*)d_in[3];
    const float *gm0  = (const float*)d_in[4],  *bt0  = (const float*)d_in[5];
    const float *W2_0 = (const float*)d_in[6],  *b2_0 = (const float*)d_in[7];
    const float *W1_1 = (const float*)d_in[8],  *b1_1 = (const float*)d_in[9];
    const float *gm1  = (const float*)d_in[10], *bt1  = (const float*)d_in[11];
    const float *W2_1 = (const float*)d_in[12], *b2_1 = (const float*)d_in[13];

    const int NND = N_NODES * D;
    float* out = (float*)d_out;
    float* h1 = out;
    float* h2 = (out_size >= 2 * NND) ? out + NND : out;

    const int ngrid = (N_NODES + 255) / 256;      // 196
    const int mgrid = (N_NODES + 31) / 32;        // 1563
    const int csr_grid = (N_EDGES + 4 * 256 - 1) / (4 * 256);   // 782

    // CSR build (edge list is identical for both layers)
    k_deg_zero<<<ngrid, 256>>>();
    k_hist<<<csr_grid, 256>>>(ei);
    k_scan<<<1, 1024>>>();
    k_fill<<<csr_grid, 256>>>(ei);

    // Layer 0
    k_gmlp1<<<mgrid, 256>>>(x, W1_0, b1_0);
    k_bnfin<<<1, D>>>(gm0, bt0);
    k_mlp2<<<mgrid, 256>>>(W2_0, b2_0, h1);

    // Layer 1 (input = h1)
    k_gmlp1<<<mgrid, 256>>>(h1, W1_1, b1_1);
    k_bnfin<<<1, D>>>(gm1, bt1);
    k_mlp2<<<mgrid, 256>>>(W2_1, b2_1, h2);
}